// round 3
// baseline (speedup 1.0000x reference)
#include <cuda_runtime.h>
#include <cstdint>

// ---------------------------------------------------------------------------
// Fused: h = x @ w^T + b ; instance-norm over OUT dim ; out = (norm(h)+y)*y
// x: [B,128] f32, w: [2048,128] f32, y/out: [B,2048] f32.  B = 32768.
//
// mma.sync m16n8k8 tf32 (arch-unconditional PTX; lowers to HMMA.TF32 on
// sm_103). M=128 rows/CTA, OUT chunked 16 x 128. Two GEMM passes:
//   pass 1: per-row sum/sumsq straight from register fragments (shfl + smem
//           atomics; no staging).
//   pass 2: recompute chunk, fused normalize + (nm+y)*y epilogue written
//           directly from fragments as 32B-aligned float2 segments.
// ---------------------------------------------------------------------------

#define DEVINL __device__ __forceinline__

static constexpr int IN      = 128;
static constexpr int OUT     = 2048;
static constexpr int MTILE   = 128;
static constexpr int NCHUNK  = 128;
static constexpr int NCHUNKS = OUT / NCHUNK;   // 16
static constexpr int THREADS = 512;            // 16 warps: 4 (m) x 4 (n)
static constexpr int TS      = 132;            // tile row stride (floats), conflict-free

// SMEM layout in floats
static constexpr int X_OFF    = 0;                 // 128 x 132
static constexpr int W_OFF    = X_OFF + 128 * TS;  // 128 x 132
static constexpr int LB_OFF   = W_OFF + 128 * TS;
static constexpr int NW_OFF   = LB_OFF + OUT;
static constexpr int NB_OFF   = NW_OFF + OUT;
static constexpr int SUM_OFF  = NB_OFF + OUT;
static constexpr int SQ_OFF   = SUM_OFF + 128;
static constexpr int MEAN_OFF = SQ_OFF + 128;
static constexpr int ISTD_OFF = MEAN_OFF + 128;
static constexpr int TOTAL_F  = ISTD_OFF + 128;
static constexpr int SMEM_BYTES = TOTAL_F * 4;     // ~158 KB

DEVINL uint32_t f2tf32(float f) {
    uint32_t r;
    asm("cvt.rna.tf32.f32 %0, %1;" : "=r"(r) : "f"(f));
    return r;
}

DEVINL void mma_tf32(float* c, uint32_t a0, uint32_t a1, uint32_t a2, uint32_t a3,
                     uint32_t b0, uint32_t b1) {
    asm volatile(
        "mma.sync.aligned.m16n8k8.row.col.f32.tf32.tf32.f32 "
        "{%0,%1,%2,%3}, {%4,%5,%6,%7}, {%8,%9}, {%0,%1,%2,%3};"
        : "+f"(c[0]), "+f"(c[1]), "+f"(c[2]), "+f"(c[3])
        : "r"(a0), "r"(a1), "r"(a2), "r"(a3), "r"(b0), "r"(b1));
}

// Load a 128x128 f32 tile (rows contiguous, ld=128) into SMEM with stride TS,
// converting each element to canonical tf32 (round-to-nearest).
DEVINL void load_tile(float* dst, const float* __restrict__ g, int tid) {
    #pragma unroll
    for (int it = 0; it < (128 * 32) / THREADS; ++it) {
        int i  = it * THREADS + tid;
        int r  = i >> 5;
        int c4 = (i & 31) * 4;
        float4 v = *reinterpret_cast<const float4*>(g + (size_t)r * IN + c4);
        float4 o;
        o.x = __uint_as_float(f2tf32(v.x));
        o.y = __uint_as_float(f2tf32(v.y));
        o.z = __uint_as_float(f2tf32(v.z));
        o.w = __uint_as_float(f2tf32(v.w));
        *reinterpret_cast<float4*>(dst + r * TS + c4) = o;
    }
}

// One 128(N-chunk) GEMM for this warp's 32x32 output tile, K=128.
DEVINL void compute_chunk(const float* __restrict__ xs, const float* __restrict__ ws,
                          int m0, int n0, int g, int tig, float acc[2][4][4]) {
    #pragma unroll
    for (int mt = 0; mt < 2; ++mt)
        #pragma unroll
        for (int nt = 0; nt < 4; ++nt)
            #pragma unroll
            for (int q = 0; q < 4; ++q)
                acc[mt][nt][q] = 0.0f;

    #pragma unroll 4
    for (int k0 = 0; k0 < 128; k0 += 8) {
        uint32_t a[2][4], b[4][2];
        #pragma unroll
        for (int mt = 0; mt < 2; ++mt) {
            const float* xr = xs + (m0 + mt * 16 + g) * TS + k0 + tig;
            a[mt][0] = __float_as_uint(xr[0]);
            a[mt][1] = __float_as_uint(xr[8 * TS]);
            a[mt][2] = __float_as_uint(xr[4]);
            a[mt][3] = __float_as_uint(xr[8 * TS + 4]);
        }
        #pragma unroll
        for (int nt = 0; nt < 4; ++nt) {
            const float* wr = ws + (n0 + nt * 8 + g) * TS + k0 + tig;
            b[nt][0] = __float_as_uint(wr[0]);
            b[nt][1] = __float_as_uint(wr[4]);
        }
        #pragma unroll
        for (int mt = 0; mt < 2; ++mt)
            #pragma unroll
            for (int nt = 0; nt < 4; ++nt)
                mma_tf32(acc[mt][nt], a[mt][0], a[mt][1], a[mt][2], a[mt][3],
                         b[nt][0], b[nt][1]);
    }
}

__global__ __launch_bounds__(THREADS, 1)
void fused_lin_inorm_kernel(const float* __restrict__ x,
                            const float* __restrict__ y,
                            const float* __restrict__ w,
                            const float* __restrict__ lb,
                            const float* __restrict__ nw,
                            const float* __restrict__ nb,
                            float* __restrict__ out) {
    extern __shared__ float sm[];
    const int tid  = threadIdx.x;
    const int wid  = tid >> 5;
    const int lane = tid & 31;
    const int g    = lane >> 2;    // groupID (row within fragment)
    const int tig  = lane & 3;     // thread-in-group (col within fragment)
    const int m0   = (wid >> 2) * 32;
    const int n0   = (wid & 3) * 32;
    const size_t row0 = (size_t)blockIdx.x * MTILE;

    // Stage parameters, zero stat accumulators, load x tile.
    #pragma unroll 1
    for (int i = tid; i < OUT; i += THREADS) {
        sm[LB_OFF + i] = lb[i];
        sm[NW_OFF + i] = nw[i];
        sm[NB_OFF + i] = nb[i];
    }
    if (tid < 128) { sm[SUM_OFF + tid] = 0.0f; sm[SQ_OFF + tid] = 0.0f; }
    load_tile(sm + X_OFF, x + row0 * IN, tid);
    __syncthreads();

    float rsum[4] = {0.f, 0.f, 0.f, 0.f};
    float rsq[4]  = {0.f, 0.f, 0.f, 0.f};

    // ---------------- PASS 1: row statistics ----------------
    for (int ch = 0; ch < NCHUNKS; ++ch) {
        load_tile(sm + W_OFF, w + (size_t)ch * NCHUNK * IN, tid);
        __syncthreads();

        float acc[2][4][4];
        compute_chunk(sm + X_OFF, sm + W_OFF, m0, n0, g, tig, acc);

        // bias for this lane's 8 columns
        float lbv[8];
        #pragma unroll
        for (int nt = 0; nt < 4; ++nt) {
            lbv[nt * 2 + 0] = sm[LB_OFF + ch * NCHUNK + n0 + nt * 8 + tig * 2 + 0];
            lbv[nt * 2 + 1] = sm[LB_OFF + ch * NCHUNK + n0 + nt * 8 + tig * 2 + 1];
        }
        #pragma unroll
        for (int mt = 0; mt < 2; ++mt)
            #pragma unroll
            for (int h = 0; h < 2; ++h)
                #pragma unroll
                for (int nt = 0; nt < 4; ++nt)
                    #pragma unroll
                    for (int p = 0; p < 2; ++p) {
                        float v = acc[mt][nt][h * 2 + p] + lbv[nt * 2 + p];
                        rsum[mt * 2 + h] += v;
                        rsq[mt * 2 + h]  += v * v;
                    }
        __syncthreads();   // protect sm_w before next chunk overwrites it
    }

    // Reduce 4 lanes per row-group, then across the 4 n-warps via smem atomics.
    #pragma unroll
    for (int j = 0; j < 4; ++j) {
        rsum[j] += __shfl_xor_sync(0xffffffffu, rsum[j], 1);
        rsum[j] += __shfl_xor_sync(0xffffffffu, rsum[j], 2);
        rsq[j]  += __shfl_xor_sync(0xffffffffu, rsq[j], 1);
        rsq[j]  += __shfl_xor_sync(0xffffffffu, rsq[j], 2);
    }
    if (tig == 0) {
        #pragma unroll
        for (int j = 0; j < 4; ++j) {
            int r = m0 + (j >> 1) * 16 + (j & 1) * 8 + g;
            atomicAdd(&sm[SUM_OFF + r], rsum[j]);
            atomicAdd(&sm[SQ_OFF + r], rsq[j]);
        }
    }
    __syncthreads();
    if (tid < 128) {
        float mean = sm[SUM_OFF + tid] * (1.0f / OUT);
        float var  = sm[SQ_OFF + tid] * (1.0f / OUT) - mean * mean;
        sm[MEAN_OFF + tid] = mean;
        sm[ISTD_OFF + tid] = rsqrtf(var + 1e-5f);
    }
    __syncthreads();

    // ---------------- PASS 2: recompute + fused epilogue ----------------
    for (int ch = 0; ch < NCHUNKS; ++ch) {
        load_tile(sm + W_OFF, w + (size_t)ch * NCHUNK * IN, tid);
        __syncthreads();

        float acc[2][4][4];
        compute_chunk(sm + X_OFF, sm + W_OFF, m0, n0, g, tig, acc);

        float lbv[8], nwv[8], nbv[8];
        #pragma unroll
        for (int nt = 0; nt < 4; ++nt)
            #pragma unroll
            for (int p = 0; p < 2; ++p) {
                int gc = ch * NCHUNK + n0 + nt * 8 + tig * 2 + p;
                lbv[nt * 2 + p] = sm[LB_OFF + gc];
                nwv[nt * 2 + p] = sm[NW_OFF + gc];
                nbv[nt * 2 + p] = sm[NB_OFF + gc];
            }
        float meanv[4], istdv[4];
        #pragma unroll
        for (int j = 0; j < 4; ++j) {
            int r = m0 + (j >> 1) * 16 + (j & 1) * 8 + g;
            meanv[j] = sm[MEAN_OFF + r];
            istdv[j] = sm[ISTD_OFF + r];
        }

        #pragma unroll
        for (int mt = 0; mt < 2; ++mt)
            #pragma unroll
            for (int h = 0; h < 2; ++h) {
                int j = mt * 2 + h;
                size_t grow = row0 + (size_t)(m0 + mt * 16 + h * 8 + g);
                const float* yr = y   + grow * OUT + ch * NCHUNK + n0 + tig * 2;
                float*       orw = out + grow * OUT + ch * NCHUNK + n0 + tig * 2;
                #pragma unroll
                for (int nt = 0; nt < 4; ++nt) {
                    float2 yv = *reinterpret_cast<const float2*>(yr + nt * 8);
                    float v0 = acc[mt][nt][h * 2 + 0] + lbv[nt * 2 + 0];
                    float v1 = acc[mt][nt][h * 2 + 1] + lbv[nt * 2 + 1];
                    float nm0 = (v0 - meanv[j]) * istdv[j] * nwv[nt * 2 + 0] + nbv[nt * 2 + 0];
                    float nm1 = (v1 - meanv[j]) * istdv[j] * nwv[nt * 2 + 1] + nbv[nt * 2 + 1];
                    float2 ov;
                    ov.x = (nm0 + yv.x) * yv.x;
                    ov.y = (nm1 + yv.y) * yv.y;
                    *reinterpret_cast<float2*>(orw + nt * 8) = ov;
                }
            }
        __syncthreads();   // protect sm_w before next chunk overwrites it
    }
}

extern "C" void kernel_launch(void* const* d_in, const int* in_sizes, int n_in,
                              void* d_out, int out_size) {
    (void)n_in; (void)out_size;
    const float* x  = (const float*)d_in[0];
    const float* y  = (const float*)d_in[1];
    const float* w  = (const float*)d_in[2];
    const float* lb = (const float*)d_in[3];
    const float* nw = (const float*)d_in[4];
    const float* nb = (const float*)d_in[5];
    float* out = (float*)d_out;

    const int rows = in_sizes[0] / IN;   // 32768
    const int grid = rows / MTILE;       // 256

    static bool configured = false;
    if (!configured) {
        cudaFuncSetAttribute(fused_lin_inorm_kernel,
                             cudaFuncAttributeMaxDynamicSharedMemorySize, SMEM_BYTES);
        configured = true;
    }
    fused_lin_inorm_kernel<<<grid, THREADS, SMEM_BYTES>>>(x, y, w, lb, nw, nb, out);
}

// round 4
// speedup vs baseline: 1.3494x; 1.3494x over previous
#include <cuda_runtime.h>
#include <cstdint>

// ---------------------------------------------------------------------------
// Fused: h = x @ w^T + b ; instance-norm over OUT ; out = (norm(h)+y)*y
// Single GEMM pass. Row stats come from the Gram identity:
//   sum_j h_ij   = x'_i . s_w + s_b
//   sum_j h_ij^2 = x'_i^T G x'_i + 2 x'_i . c + d
// with G = sum_j w'_j w'_j^T, c = sum_j b_j w'_j, built from tf32-TRUNCATED
// w' (exactly the operand HMMA.TF32 consumes), so stats match h consistently.
// w chunks stream via double-buffered cp.async; x is cvt.rna'd once into smem.
// ---------------------------------------------------------------------------

#define DEVINL __device__ __forceinline__

static constexpr int IN      = 128;
static constexpr int OUT     = 2048;
static constexpr int MTILE   = 128;
static constexpr int NCHUNK  = 128;
static constexpr int NCHUNKS = OUT / NCHUNK;   // 16
static constexpr int THREADS = 512;            // 16 warps: 4 (m) x 4 (n)
static constexpr int TS      = 132;            // smem tile row stride (floats)

// SMEM layout (floats)
static constexpr int X_OFF    = 0;                  // 128 x 132
static constexpr int W0_OFF   = X_OFF + 128 * TS;   // buf 0
static constexpr int W1_OFF   = W0_OFF + 128 * TS;  // buf 1
static constexpr int MEAN_OFF = W1_OFF + 128 * TS;
static constexpr int DOTC_OFF = MEAN_OFF + 128;
static constexpr int SQ_OFF   = DOTC_OFF + 128;
static constexpr int ISTD_OFF = SQ_OFF + 128;
static constexpr int TOTAL_F  = ISTD_OFF + 128;
static constexpr int SMEM_BYTES = TOTAL_F * 4;      // 204.8 KB

// ---- device scratch (static allocation: allowed) ----
__device__ float g_G[IN * IN];   // Gram matrix of truncated w rows
__device__ float g_c[IN];        // sum_j b_j w'_j
__device__ float g_sw[IN];       // sum_j w'_j
__device__ float g_db[2];        // [0] = sum b^2, [1] = sum b

DEVINL float tf32_trunc(float f) {
    return __uint_as_float(__float_as_uint(f) & 0xFFFFE000u);
}
DEVINL uint32_t f2tf32(float f) {
    uint32_t r;
    asm("cvt.rna.tf32.f32 %0, %1;" : "=r"(r) : "f"(f));
    return r;
}
DEVINL uint32_t smem_u32(const void* p) {
    uint32_t a;
    asm("{ .reg .u64 t; cvta.to.shared.u64 t, %1; cvt.u32.u64 %0, t; }"
        : "=r"(a) : "l"(p));
    return a;
}
DEVINL void cp_async16(uint32_t saddr, const void* g) {
    asm volatile("cp.async.cg.shared.global [%0], [%1], 16;" :: "r"(saddr), "l"(g));
}
#define CP_COMMIT() asm volatile("cp.async.commit_group;" ::: "memory")
#define CP_WAIT(n)  asm volatile("cp.async.wait_group %0;" :: "n"(n) : "memory")

DEVINL void mma_tf32(float* c, uint32_t a0, uint32_t a1, uint32_t a2, uint32_t a3,
                     uint32_t b0, uint32_t b1) {
    asm volatile(
        "mma.sync.aligned.m16n8k8.row.col.f32.tf32.tf32.f32 "
        "{%0,%1,%2,%3}, {%4,%5,%6,%7}, {%8,%9}, {%0,%1,%2,%3};"
        : "+f"(c[0]), "+f"(c[1]), "+f"(c[2]), "+f"(c[3])
        : "r"(a0), "r"(a1), "r"(a2), "r"(a3), "r"(b0), "r"(b1));
}

// ---------------- precompute kernels ----------------

__global__ void zero_scratch_kernel() {
    int i = blockIdx.x * blockDim.x + threadIdx.x;
    if (i < IN * IN) g_G[i] = 0.0f;
    if (i < IN) { g_c[i] = 0.0f; g_sw[i] = 0.0f; }
    if (i < 2)  g_db[i] = 0.0f;
}

__global__ __launch_bounds__(256, 1)
void gram_kernel(const float* __restrict__ w, const float* __restrict__ b) {
    __shared__ float ws[32][IN];
    __shared__ float bs[32];
    const int tid   = threadIdx.x;
    const int jbase = blockIdx.x * 32;

    #pragma unroll
    for (int it = 0; it < 4; ++it) {
        int i  = it * 256 + tid;             // 1024 float4 slots
        int j  = i >> 5;
        int c4 = (i & 31) * 4;
        float4 v = *reinterpret_cast<const float4*>(w + (size_t)(jbase + j) * IN + c4);
        ws[j][c4 + 0] = tf32_trunc(v.x);
        ws[j][c4 + 1] = tf32_trunc(v.y);
        ws[j][c4 + 2] = tf32_trunc(v.z);
        ws[j][c4 + 3] = tf32_trunc(v.w);
    }
    if (tid < 32) bs[tid] = b[jbase + tid];
    __syncthreads();

    const int k     = tid & 127;
    const int lbase = (tid >> 7) * 64;
    float acc[64];
    #pragma unroll
    for (int l = 0; l < 64; ++l) acc[l] = 0.0f;
    float ck = 0.0f, swk = 0.0f;

    for (int j = 0; j < 32; ++j) {
        float wk = ws[j][k];
        #pragma unroll
        for (int l = 0; l < 64; ++l) acc[l] += wk * ws[j][lbase + l];
        ck  += bs[j] * wk;
        swk += wk;
    }
    #pragma unroll
    for (int l = 0; l < 64; ++l) atomicAdd(&g_G[k * IN + lbase + l], acc[l]);
    if (tid < IN) { atomicAdd(&g_c[k], ck); atomicAdd(&g_sw[k], swk); }
    if (tid < 32) {
        atomicAdd(&g_db[0], bs[tid] * bs[tid]);
        atomicAdd(&g_db[1], bs[tid]);
    }
}

// ---------------- main kernel ----------------

// Swizzle-free padded store offsets; conflict-free fragment reads (TS=132).
DEVINL void load_x_tile(float* dst, const float* __restrict__ g, int tid) {
    #pragma unroll
    for (int it = 0; it < (128 * 32) / THREADS; ++it) {
        int i  = it * THREADS + tid;
        int r  = i >> 5;
        int c4 = (i & 31) * 4;
        float4 v = *reinterpret_cast<const float4*>(g + (size_t)r * IN + c4);
        float4 o;
        o.x = __uint_as_float(f2tf32(v.x));
        o.y = __uint_as_float(f2tf32(v.y));
        o.z = __uint_as_float(f2tf32(v.z));
        o.w = __uint_as_float(f2tf32(v.w));
        *reinterpret_cast<float4*>(dst + r * TS + c4) = o;
    }
}

DEVINL void issue_w_chunk(uint32_t sbase_f, const float* __restrict__ g, int tid) {
    #pragma unroll
    for (int it = 0; it < (128 * 32) / THREADS; ++it) {
        int i  = it * THREADS + tid;
        int r  = i >> 5;
        int c4 = (i & 31) * 4;
        cp_async16(sbase_f + (uint32_t)(r * TS + c4) * 4u, g + (size_t)r * IN + c4);
    }
}

DEVINL void compute_chunk(const float* __restrict__ xs, const float* __restrict__ ws,
                          int m0, int n0, int g, int tig, float acc[2][4][4]) {
    #pragma unroll
    for (int mt = 0; mt < 2; ++mt)
        #pragma unroll
        for (int nt = 0; nt < 4; ++nt)
            #pragma unroll
            for (int q = 0; q < 4; ++q)
                acc[mt][nt][q] = 0.0f;

    #pragma unroll 4
    for (int k0 = 0; k0 < 128; k0 += 8) {
        uint32_t a[2][4], b[4][2];
        #pragma unroll
        for (int mt = 0; mt < 2; ++mt) {
            const float* xr = xs + (m0 + mt * 16 + g) * TS + k0 + tig;
            a[mt][0] = __float_as_uint(xr[0]);
            a[mt][1] = __float_as_uint(xr[8 * TS]);
            a[mt][2] = __float_as_uint(xr[4]);
            a[mt][3] = __float_as_uint(xr[8 * TS + 4]);
        }
        #pragma unroll
        for (int nt = 0; nt < 4; ++nt) {
            const float* wr = ws + (n0 + nt * 8 + g) * TS + k0 + tig;
            b[nt][0] = __float_as_uint(wr[0]);
            b[nt][1] = __float_as_uint(wr[4]);
        }
        #pragma unroll
        for (int mt = 0; mt < 2; ++mt)
            #pragma unroll
            for (int nt = 0; nt < 4; ++nt)
                mma_tf32(acc[mt][nt], a[mt][0], a[mt][1], a[mt][2], a[mt][3],
                         b[nt][0], b[nt][1]);
    }
}

__global__ __launch_bounds__(THREADS, 1)
void fused_lin_inorm_kernel(const float* __restrict__ x,
                            const float* __restrict__ y,
                            const float* __restrict__ w,
                            const float* __restrict__ lb,
                            const float* __restrict__ nw,
                            const float* __restrict__ nb,
                            float* __restrict__ out) {
    extern __shared__ float sm[];
    const int tid  = threadIdx.x;
    const int wid  = tid >> 5;
    const int lane = tid & 31;
    const int g    = lane >> 2;
    const int tig  = lane & 3;
    const int m0   = (wid >> 2) * 32;
    const int n0   = (wid & 3) * 32;
    const size_t row0 = (size_t)blockIdx.x * MTILE;

    float* xs  = sm + X_OFF;
    float* wb0 = sm + W0_OFF;
    float* wb1 = sm + W1_OFF;
    const uint32_t sb_u32 = smem_u32(sm);
    const uint32_t w0_u32 = sb_u32 + W0_OFF * 4;
    const uint32_t w1_u32 = sb_u32 + W1_OFF * 4;

    if (tid < 128) sm[SQ_OFF + tid] = 0.0f;

    // G into buf0 (raw f32 via cp.async; already truncated in precompute)
    issue_w_chunk(w0_u32, g_G, tid);
    CP_COMMIT();

    load_x_tile(xs, x + row0 * IN, tid);
    __syncthreads();   // x' + sm_sq zeros visible

    // Per-row mean and x'.c while G streams in.
    if (tid < 128) {
        float dm = 0.0f, dc = 0.0f;
        const float* xr = xs + tid * TS;
        #pragma unroll 8
        for (int k = 0; k < IN; ++k) {
            float xv = xr[k];
            dm += xv * g_sw[k];
            dc += xv * g_c[k];
        }
        sm[MEAN_OFF + tid] = (dm + g_db[1]) * (1.0f / OUT);
        sm[DOTC_OFF + tid] = dc;
    }

    CP_WAIT(0);
    __syncthreads();   // G tile visible

    // Kick off w chunk 0 into buf1, then compute Z = x' @ G on buf0.
    issue_w_chunk(w1_u32, w, tid);
    CP_COMMIT();

    {
        float acc[2][4][4];
        compute_chunk(xs, wb0, m0, n0, g, tig, acc);
        float rsq[4] = {0.f, 0.f, 0.f, 0.f};
        #pragma unroll
        for (int mt = 0; mt < 2; ++mt)
            #pragma unroll
            for (int h = 0; h < 2; ++h) {
                int r = m0 + mt * 16 + h * 8 + g;
                const float* xrow = xs + r * TS;
                #pragma unroll
                for (int nt = 0; nt < 4; ++nt)
                    #pragma unroll
                    for (int p = 0; p < 2; ++p) {
                        int col = n0 + nt * 8 + tig * 2 + p;
                        rsq[mt * 2 + h] += acc[mt][nt][h * 2 + p] * xrow[col];
                    }
            }
        #pragma unroll
        for (int j = 0; j < 4; ++j) {
            rsq[j] += __shfl_xor_sync(0xffffffffu, rsq[j], 1);
            rsq[j] += __shfl_xor_sync(0xffffffffu, rsq[j], 2);
        }
        if (tig == 0) {
            #pragma unroll
            for (int j = 0; j < 4; ++j) {
                int r = m0 + (j >> 1) * 16 + (j & 1) * 8 + g;
                atomicAdd(&sm[SQ_OFF + r], rsq[j]);
            }
        }
    }
    __syncthreads();   // sm_sq complete; buf0 free

    if (tid < 128) {
        float sumsq = sm[SQ_OFF + tid] + 2.0f * sm[DOTC_OFF + tid] + g_db[0];
        float mean  = sm[MEAN_OFF + tid];
        float var   = sumsq * (1.0f / OUT) - mean * mean;
        sm[ISTD_OFF + tid] = rsqrtf(var + 1e-5f);
    }
    __syncthreads();

    // Hoist per-row norm params into registers (constant across chunks).
    float meanv[4], istdv[4];
    #pragma unroll
    for (int j = 0; j < 4; ++j) {
        int r = m0 + (j >> 1) * 16 + (j & 1) * 8 + g;
        meanv[j] = sm[MEAN_OFF + r];
        istdv[j] = sm[ISTD_OFF + r];
    }

    // ---------------- single GEMM pass, double-buffered ----------------
    for (int ch = 0; ch < NCHUNKS; ++ch) {
        if (ch < NCHUNKS - 1) {
            issue_w_chunk((ch & 1) ? w1_u32 : w0_u32,
                          w + (size_t)(ch + 1) * NCHUNK * IN, tid);
            CP_COMMIT();
            CP_WAIT(1);
        } else {
            CP_WAIT(0);
        }
        __syncthreads();   // chunk ch visible in wb[(ch+1)&1]

        const float* wbuf = ((ch + 1) & 1) ? wb1 : wb0;
        float acc[2][4][4];
        compute_chunk(xs, wbuf, m0, n0, g, tig, acc);

        const int gcb = ch * NCHUNK + n0 + tig * 2;
        float2 lbv[4], nwv[4], nbv[4];
        #pragma unroll
        for (int nt = 0; nt < 4; ++nt) {
            lbv[nt] = __ldg(reinterpret_cast<const float2*>(lb + gcb + nt * 8));
            nwv[nt] = __ldg(reinterpret_cast<const float2*>(nw + gcb + nt * 8));
            nbv[nt] = __ldg(reinterpret_cast<const float2*>(nb + gcb + nt * 8));
        }

        #pragma unroll
        for (int mt = 0; mt < 2; ++mt)
            #pragma unroll
            for (int h = 0; h < 2; ++h) {
                int j = mt * 2 + h;
                size_t grow = row0 + (size_t)(m0 + mt * 16 + h * 8 + g);
                const float* yr  = y   + grow * OUT + gcb;
                float*       orw = out + grow * OUT + gcb;
                #pragma unroll
                for (int nt = 0; nt < 4; ++nt) {
                    float2 yv = *reinterpret_cast<const float2*>(yr + nt * 8);
                    float v0 = acc[mt][nt][h * 2 + 0] + lbv[nt].x;
                    float v1 = acc[mt][nt][h * 2 + 1] + lbv[nt].y;
                    float nm0 = (v0 - meanv[j]) * istdv[j] * nwv[nt].x + nbv[nt].x;
                    float nm1 = (v1 - meanv[j]) * istdv[j] * nwv[nt].y + nbv[nt].y;
                    float2 ov;
                    ov.x = (nm0 + yv.x) * yv.x;
                    ov.y = (nm1 + yv.y) * yv.y;
                    *reinterpret_cast<float2*>(orw + nt * 8) = ov;
                }
            }
        __syncthreads();   // release wbuf before it is overwritten
    }
}

extern "C" void kernel_launch(void* const* d_in, const int* in_sizes, int n_in,
                              void* d_out, int out_size) {
    (void)n_in; (void)out_size;
    const float* x  = (const float*)d_in[0];
    const float* y  = (const float*)d_in[1];
    const float* w  = (const float*)d_in[2];
    const float* lb = (const float*)d_in[3];
    const float* nw = (const float*)d_in[4];
    const float* nb = (const float*)d_in[5];
    float* out = (float*)d_out;

    const int rows = in_sizes[0] / IN;   // 32768
    const int grid = rows / MTILE;       // 256

    static bool configured = false;
    if (!configured) {
        cudaFuncSetAttribute(fused_lin_inorm_kernel,
                             cudaFuncAttributeMaxDynamicSharedMemorySize, SMEM_BYTES);
        configured = true;
    }

    zero_scratch_kernel<<<64, 256>>>();
    gram_kernel<<<OUT / 32, 256>>>(w, lb);
    fused_lin_inorm_kernel<<<grid, THREADS, SMEM_BYTES>>>(x, y, w, lb, nw, nb, out);
}